// round 5
// baseline (speedup 1.0000x reference)
#include <cuda_runtime.h>
#include <cuda_fp16.h>
#include <cstdint>

#define DEV __device__ __forceinline__

// ---------------- problem constants ----------------
static constexpr int HID    = 128;
static constexpr int BATCH  = 128;
static constexpr int NROWS  = 128 * 4096;     // 524288
static constexpr int NT2    = NROWS / 256;    // 2048 tiles of 256 rows

// ---------------- SMEM layout (byte offsets) ----------------
static constexpr int OFF_BAR  = 0;                  // mbarrier (8B)
static constexpr int OFF_W3   = 64;                 // 64 f32
static constexpr int OFF_B2C  = 320;                // 64 f32
static constexpr int OFF_B3   = 576;                // 1 f32
static constexpr int OFF_CS   = 1024;               // [2][256] f32 (2KB)
static constexpr int OFF_A1   = 3072;               // 256 x 128 f16 swizzled (64KB)
static constexpr int OFF_B1   = OFF_A1 + 65536;     // 256n x 128k f16 swizzled (64KB)
static constexpr int OFF_B2   = OFF_B1 + 65536;     // 64n x 256k f16 swizzled (32KB)
static constexpr int OFF_STG  = OFF_B2 + 32768;     // fp32 stage: 128 rows x 128 (64KB)
static constexpr int SMEM_BYTES = OFF_STG + 65536;  // 232448 == opt-in max

// ---------------- helpers ----------------
DEV uint32_t s2u(const void* p) {
    uint32_t a;
    asm("{ .reg .u64 t; cvta.to.shared.u64 t, %1; cvt.u32.u64 %0, t; }" : "=r"(a) : "l"(p));
    return a;
}
DEV uint32_t pack2(float a, float b) {
    __half2 h = __floats2half2_rn(a, b);
    return *reinterpret_cast<uint32_t*>(&h);
}
DEV void mbar_init(uint32_t mbar, uint32_t cnt) {
    asm volatile("mbarrier.init.shared.b64 [%0], %1;" :: "r"(mbar), "r"(cnt) : "memory");
}
DEV void mbar_expect(uint32_t mbar, uint32_t bytes) {
    asm volatile("mbarrier.arrive.expect_tx.shared.b64 _, [%0], %1;" :: "r"(mbar), "r"(bytes) : "memory");
}
DEV void mbar_wait(uint32_t mbar, uint32_t parity) {
    asm volatile(
        "{\n\t.reg .pred P;\n\t"
        "LW%=:\n\t"
        "mbarrier.try_wait.parity.acquire.cta.shared::cta.b64 P, [%0], %1, 0x989680;\n\t"
        "@P bra LD%=;\n\t"
        "bra LW%=;\n\t"
        "LD%=:\n\t}"
        :: "r"(mbar), "r"(parity) : "memory");
}
DEV void bulk_g2s(uint32_t dst, const void* src, uint32_t bytes, uint32_t mbar) {
    asm volatile(
        "cp.async.bulk.shared::cta.global.mbarrier::complete_tx::bytes [%0], [%1], %2, [%3];"
        :: "r"(dst), "l"(src), "r"(bytes), "r"(mbar) : "memory");
}
DEV void ldsm4(uint32_t* r, uint32_t addr) {
    asm volatile("ldmatrix.sync.aligned.m8n8.x4.shared.b16 {%0,%1,%2,%3}, [%4];"
        : "=r"(r[0]), "=r"(r[1]), "=r"(r[2]), "=r"(r[3]) : "r"(addr));
}
DEV void mma16816(float* c, const uint32_t* a, uint32_t b0, uint32_t b1) {
    asm volatile(
        "mma.sync.aligned.m16n8k16.row.col.f32.f16.f16.f32 "
        "{%0,%1,%2,%3}, {%4,%5,%6,%7}, {%8,%9}, {%0,%1,%2,%3};"
        : "+f"(c[0]), "+f"(c[1]), "+f"(c[2]), "+f"(c[3])
        : "r"(a[0]), "r"(a[1]), "r"(a[2]), "r"(a[3]), "r"(b0), "r"(b1));
}
DEV void named_bar(int id) {
    asm volatile("bar.sync %0, 128;" :: "r"(id) : "memory");
}
DEV void sts64(uint32_t addr, uint32_t lo, uint32_t hi) {
    asm volatile("st.shared.v2.u32 [%0], {%1, %2};" :: "r"(addr), "r"(lo), "r"(hi) : "memory");
}

// ---------------- per-batch bias: c[b] = b1 + new_nodes[b] @ W1[128:256] ----------------
__device__ float g_cbias[BATCH * 256];

__global__ void cbias_kernel(const float* __restrict__ new_nodes,
                             const float* __restrict__ W1,
                             const float* __restrict__ b1) {
    int b = blockIdx.x;
    int n = threadIdx.x;
    float acc = b1[n];
    const float* nb = new_nodes + (size_t)b * HID;
#pragma unroll 8
    for (int f = 0; f < HID; ++f)
        acc = fmaf(nb[f], W1[(size_t)(HID + f) * 256 + n], acc);
    g_cbias[b * 256 + n] = acc;
}

// ---------------- main fused kernel ----------------
__global__ void __launch_bounds__(256, 1)
edge_mlp_kernel(const float* __restrict__ nodes,   // [NROWS,128]
                const float* __restrict__ W1,      // [256,256]
                const float* __restrict__ W2,      // [256,64]
                const float* __restrict__ W3,      // [64]
                const float* __restrict__ b2,      // [64]
                const float* __restrict__ b3,      // [1]
                float* __restrict__ out)           // [NROWS]
{
    extern __shared__ char smem[];
    const uint32_t sb = s2u(smem);
    const int tid  = threadIdx.x;
    const int wid  = tid >> 5;
    const int lane = tid & 31;
    const int l7   = lane & 7;
    const int l3   = lane & 3;
    const int rsel = (lane >> 3) & 1;   // row-half selector for ldmatrix
    const int usub = lane >> 4;         // k-unit selector for ldmatrix
    const int g    = tid >> 7;          // group 0: warps 0-3 (rows 0-127); group 1: warps 4-7
    const int gtid = tid & 127;

    float* w3_s = reinterpret_cast<float*>(smem + OFF_W3);
    float* b2_s = reinterpret_cast<float*>(smem + OFF_B2C);
    float* b3_s = reinterpret_cast<float*>(smem + OFF_B3);
    float* cs_g = reinterpret_cast<float*>(smem + OFF_CS) + g * 256;
    float* stg  = reinterpret_cast<float*>(smem + OFF_STG);

    const uint32_t sbar = sb + OFF_BAR;

    if (tid == 0) mbar_init(sbar, 1);
    __syncthreads();

    // load 0: tile blockIdx.x, rows [0,128) — issued ASAP, overlaps weight conversion
    if (tid == 0) {
        mbar_expect(sbar, 65536);
        bulk_g2s(sb + OFF_STG, nodes + (size_t)blockIdx.x * (256 * HID), 65536, sbar);
    }

    // small constants
    if (tid < 64) { w3_s[tid] = W3[tid]; b2_s[tid] = b2[tid]; }
    if (tid == 0) b3_s[0] = b3[0];

    // B1: [n=256][k=128] f16, 256B rows, XOR swizzle (unit16B ^ row&7). B1[n][k]=W1[k*256+n]
    {
        const int n = tid;
#pragma unroll 4
        for (int kp = 0; kp < 64; ++kp) {
            float a = W1[(size_t)(2 * kp) * 256 + n];
            float b = W1[(size_t)(2 * kp + 1) * 256 + n];
            uint32_t addr = (uint32_t)(n * 256 + (((kp >> 2) ^ (n & 7)) << 4) + (kp & 3) * 4);
            *reinterpret_cast<uint32_t*>(smem + OFF_B1 + addr) = pack2(a, b);
        }
    }
    // B2: [n=64][k=256] f16, 512B rows, same swizzle. B2[n][k]=W2[k*64+n]
    {
#pragma unroll 4
        for (int j = 0; j < 32; ++j) {
            int idx = tid + j * 256;
            int n  = idx & 63;
            int kp = idx >> 6;              // 0..127
            float a = W2[(size_t)(2 * kp) * 64 + n];
            float b = W2[(size_t)(2 * kp + 1) * 64 + n];
            uint32_t addr = (uint32_t)(n * 512 + (((kp >> 2) ^ (n & 7)) << 4) + (kp & 3) * 4);
            *reinterpret_cast<uint32_t*>(smem + OFF_B2 + addr) = pack2(a, b);
        }
    }
    __syncthreads();
    // after this point: NO full-CTA barriers; the two groups run decoupled.

    // per-warp ldmatrix lane bases
    const uint32_t aBase0 = sb + OFF_A1 + (uint32_t)((wid * 32      + l7 + (rsel << 3)) * 256);
    const uint32_t aBase1 = sb + OFF_A1 + (uint32_t)((wid * 32 + 16 + l7 + (rsel << 3)) * 256);
    const uint32_t b1LaneBase = sb + OFF_B1 + (uint32_t)((l7 + (rsel << 3)) * 256);
    const uint32_t b2LaneBase = sb + OFF_B2 + (uint32_t)((l7 + (rsel << 3)) * 512);

    const int grid = gridDim.x;

    for (int t = blockIdx.x; t < NT2; t += grid) {
        // ---- wait my group's staged half (parity == g by construction) ----
        mbar_wait(sbar, (uint32_t)g);

        // per-tile bias into group-private copy (batch constant across the tile)
        const int b = t >> 4;
        cs_g[gtid]       = g_cbias[b * 256 + gtid];
        cs_g[gtid + 128] = g_cbias[b * 256 + 128 + gtid];

        // ---- convert stage fp32 -> f16 swizzled A1 rows [g*128, g*128+128) ----
        // two k-pairs per iteration: float4 load + STS.64 (same 16B swizzle unit)
#pragma unroll 4
        for (int j = 0; j < 32; ++j) {
            int idx = gtid + j * 128;                // 0..4095
            int m   = idx >> 5;                      // local row 0..127
            int kp2 = idx & 31;                      // pair-of-pairs 0..31
            float4 v = reinterpret_cast<const float4*>(stg)[m * 32 + kp2];
            uint32_t lo = pack2(v.x, v.y);
            uint32_t hi = pack2(v.z, v.w);
            int kp = kp2 * 2;
            uint32_t addr = sb + OFF_A1 +
                (uint32_t)((g * 128 + m) * 256 + (((kp >> 2) ^ (m & 7)) << 4) + (kp & 3) * 4);
            sts64(addr, lo, hi);
        }
        named_bar(1 + g);

        // ---- group leader issues the NEXT load (stage buffer now free) ----
        if (gtid == 0) {
            if (g == 0) {
                mbar_expect(sbar, 65536);
                bulk_g2s(sb + OFF_STG, nodes + ((size_t)t * 256 + 128) * HID, 65536, sbar);
            } else if (t + grid < NT2) {
                mbar_expect(sbar, 65536);
                bulk_g2s(sb + OFF_STG, nodes + (size_t)(t + grid) * 256 * HID, 65536, sbar);
            }
        }

        // ---- load A fragments: 32 rows x 128 k -> 2 halves x 8 k-steps ----
        uint32_t areg[2][8][4];
#pragma unroll
        for (int s = 0; s < 8; ++s) {
            ldsm4(areg[0][s], aBase0 + (uint32_t)((((s << 1) + usub) ^ l7) << 4));
            ldsm4(areg[1][s], aBase1 + (uint32_t)((((s << 1) + usub) ^ l7) << 4));
        }

        float c2[2][8][4];
#pragma unroll
        for (int h = 0; h < 2; ++h)
#pragma unroll
            for (int f = 0; f < 8; ++f)
#pragma unroll
                for (int q = 0; q < 4; ++q) c2[h][f][q] = 0.f;

        // ---- fused layers 1+2, p = 16-col block of layer-1 output (FULLY UNROLLED) ----
#pragma unroll
        for (int p = 0; p < 16; ++p) {
            float c1[2][2][4];
#pragma unroll
            for (int h = 0; h < 2; ++h)
#pragma unroll
                for (int n = 0; n < 2; ++n)
#pragma unroll
                    for (int q = 0; q < 4; ++q) c1[h][n][q] = 0.f;

            const uint32_t bB = b1LaneBase + (uint32_t)(p * 16 * 256);
#pragma unroll
            for (int s = 0; s < 8; ++s) {
                uint32_t br[4];
                ldsm4(br, bB + (uint32_t)((((s << 1) + usub) ^ l7) << 4));
                mma16816(c1[0][0], areg[0][s], br[0], br[2]);
                mma16816(c1[0][1], areg[0][s], br[1], br[3]);
                mma16816(c1[1][0], areg[1][s], br[0], br[2]);
                mma16816(c1[1][1], areg[1][s], br[1], br[3]);
            }

            // epilogue-1 in registers: relu(+c) -> pack f16 -> layer-2 A frags
            float2 cva = *reinterpret_cast<const float2*>(&cs_g[p * 16 + l3 * 2]);
            float2 cvb = *reinterpret_cast<const float2*>(&cs_g[p * 16 + 8 + l3 * 2]);
            uint32_t a2[2][4];
#pragma unroll
            for (int h = 0; h < 2; ++h) {
                a2[h][0] = pack2(fmaxf(c1[h][0][0] + cva.x, 0.f), fmaxf(c1[h][0][1] + cva.y, 0.f));
                a2[h][1] = pack2(fmaxf(c1[h][0][2] + cva.x, 0.f), fmaxf(c1[h][0][3] + cva.y, 0.f));
                a2[h][2] = pack2(fmaxf(c1[h][1][0] + cvb.x, 0.f), fmaxf(c1[h][1][1] + cvb.y, 0.f));
                a2[h][3] = pack2(fmaxf(c1[h][1][2] + cvb.x, 0.f), fmaxf(c1[h][1][3] + cvb.y, 0.f));
            }

            // layer-2 partial: k-step p
            const uint32_t koff = (uint32_t)((((p << 1) + usub) ^ l7) << 4);
#pragma unroll
            for (int p2 = 0; p2 < 4; ++p2) {
                uint32_t br2[4];
                ldsm4(br2, b2LaneBase + (uint32_t)(p2 * 16 * 512) + koff);
                mma16816(c2[0][2 * p2],     a2[0], br2[0], br2[2]);
                mma16816(c2[0][2 * p2 + 1], a2[0], br2[1], br2[3]);
                mma16816(c2[1][2 * p2],     a2[1], br2[0], br2[2]);
                mma16816(c2[1][2 * p2 + 1], a2[1], br2[1], br2[3]);
            }
        }

        // ---- epilogue 2: relu(C2 + b2) . W3 + b3 -> sigmoid -> out ----
        const float bias3 = b3_s[0];
#pragma unroll
        for (int h = 0; h < 2; ++h) {
            float accl = 0.f, acch = 0.f;
#pragma unroll
            for (int f2 = 0; f2 < 8; ++f2) {
                const int col = f2 * 8 + l3 * 2;
                float w0 = w3_s[col], w1 = w3_s[col + 1];
                float bb0 = b2_s[col], bb1 = b2_s[col + 1];
                accl = fmaf(fmaxf(c2[h][f2][0] + bb0, 0.f), w0, accl);
                accl = fmaf(fmaxf(c2[h][f2][1] + bb1, 0.f), w1, accl);
                acch = fmaf(fmaxf(c2[h][f2][2] + bb0, 0.f), w0, acch);
                acch = fmaf(fmaxf(c2[h][f2][3] + bb1, 0.f), w1, acch);
            }
            accl += __shfl_xor_sync(0xffffffffu, accl, 1);
            accl += __shfl_xor_sync(0xffffffffu, accl, 2);
            acch += __shfl_xor_sync(0xffffffffu, acch, 1);
            acch += __shfl_xor_sync(0xffffffffu, acch, 2);
            if (l3 == 0) {
                const int row = t * 256 + wid * 32 + 16 * h + (lane >> 2);
                out[row]     = 1.f / (1.f + __expf(-(accl + bias3)));
                out[row + 8] = 1.f / (1.f + __expf(-(acch + bias3)));
            }
        }

        named_bar(1 + g);   // protect cs_g (and ordering) for the next iteration
    }
}

// ---------------- launch ----------------
extern "C" void kernel_launch(void* const* d_in, const int* in_sizes, int n_in,
                              void* d_out, int out_size) {
    const float* nodes = (const float*)d_in[0];   // [128,4096,128]
    const float* newn  = (const float*)d_in[1];   // [128,1,128]
    const float* W1    = (const float*)d_in[2];   // [256,256]
    const float* b1    = (const float*)d_in[3];   // [256]
    const float* W2    = (const float*)d_in[4];   // [256,64]
    const float* b2    = (const float*)d_in[5];   // [64]
    const float* W3    = (const float*)d_in[6];   // [64,1]
    const float* b3    = (const float*)d_in[7];   // [1]
    float* out = (float*)d_out;

    (void)in_sizes; (void)n_in; (void)out_size;

    cudaFuncSetAttribute(edge_mlp_kernel,
                         cudaFuncAttributeMaxDynamicSharedMemorySize, SMEM_BYTES);

    int nsm = 148;
    cudaDeviceGetAttribute(&nsm, cudaDevAttrMultiProcessorCount, 0);
    if (nsm <= 0) nsm = 148;
    if (nsm > NT2) nsm = NT2;

    cbias_kernel<<<BATCH, 256>>>(newn, W1, b1);
    edge_mlp_kernel<<<nsm, 256, SMEM_BYTES>>>(nodes, W1, W2, W3, b2, b3, out);
}

// round 6
// speedup vs baseline: 1.1412x; 1.1412x over previous
#include <cuda_runtime.h>
#include <cuda_fp16.h>
#include <cstdint>

#define DEV __device__ __forceinline__

// ---------------- problem constants ----------------
static constexpr int HID    = 128;
static constexpr int BATCH  = 128;
static constexpr int NROWS  = 128 * 4096;     // 524288
static constexpr int NT2    = NROWS / 256;    // 2048 tiles of 256 rows

// ---------------- SMEM layout (byte offsets) ----------------
static constexpr int OFF_BAR  = 0;                  // mbarrier (8B)
static constexpr int OFF_W3   = 64;                 // 64 f32
static constexpr int OFF_B2C  = 320;                // 64 f32
static constexpr int OFF_B3   = 576;                // 1 f32
static constexpr int OFF_CS   = 1024;               // [2][256] f32 (2KB)
static constexpr int OFF_A1   = 3072;               // 256 x 128 f16 swizzled (64KB)
static constexpr int OFF_B1   = OFF_A1 + 65536;     // 256n x 128k f16 swizzled (64KB)
static constexpr int OFF_B2   = OFF_B1 + 65536;     // 64n x 256k f16 swizzled (32KB)
static constexpr int OFF_STG  = OFF_B2 + 32768;     // fp32 stage: 128 rows x 128 (64KB)
static constexpr int SMEM_BYTES = OFF_STG + 65536;  // 232448 == opt-in max

// ---------------- helpers ----------------
DEV uint32_t s2u(const void* p) {
    uint32_t a;
    asm("{ .reg .u64 t; cvta.to.shared.u64 t, %1; cvt.u32.u64 %0, t; }" : "=r"(a) : "l"(p));
    return a;
}
DEV uint32_t pack2(float a, float b) {
    __half2 h = __floats2half2_rn(a, b);
    return *reinterpret_cast<uint32_t*>(&h);
}
DEV void mbar_init(uint32_t mbar, uint32_t cnt) {
    asm volatile("mbarrier.init.shared.b64 [%0], %1;" :: "r"(mbar), "r"(cnt) : "memory");
}
DEV void mbar_expect(uint32_t mbar, uint32_t bytes) {
    asm volatile("mbarrier.arrive.expect_tx.shared.b64 _, [%0], %1;" :: "r"(mbar), "r"(bytes) : "memory");
}
DEV void mbar_wait(uint32_t mbar, uint32_t parity) {
    asm volatile(
        "{\n\t.reg .pred P;\n\t"
        "LW%=:\n\t"
        "mbarrier.try_wait.parity.acquire.cta.shared::cta.b64 P, [%0], %1, 0x989680;\n\t"
        "@P bra LD%=;\n\t"
        "bra LW%=;\n\t"
        "LD%=:\n\t}"
        :: "r"(mbar), "r"(parity) : "memory");
}
DEV void bulk_g2s(uint32_t dst, const void* src, uint32_t bytes, uint32_t mbar) {
    asm volatile(
        "cp.async.bulk.shared::cta.global.mbarrier::complete_tx::bytes [%0], [%1], %2, [%3];"
        :: "r"(dst), "l"(src), "r"(bytes), "r"(mbar) : "memory");
}
DEV void ldsm4(uint32_t* r, uint32_t addr) {
    asm volatile("ldmatrix.sync.aligned.m8n8.x4.shared.b16 {%0,%1,%2,%3}, [%4];"
        : "=r"(r[0]), "=r"(r[1]), "=r"(r[2]), "=r"(r[3]) : "r"(addr));
}
DEV void mma16816(float* c, const uint32_t* a, uint32_t b0, uint32_t b1) {
    asm volatile(
        "mma.sync.aligned.m16n8k16.row.col.f32.f16.f16.f32 "
        "{%0,%1,%2,%3}, {%4,%5,%6,%7}, {%8,%9}, {%0,%1,%2,%3};"
        : "+f"(c[0]), "+f"(c[1]), "+f"(c[2]), "+f"(c[3])
        : "r"(a[0]), "r"(a[1]), "r"(a[2]), "r"(a[3]), "r"(b0), "r"(b1));
}
DEV void named_bar(int id) {
    asm volatile("bar.sync %0, 128;" :: "r"(id) : "memory");
}
DEV void sts64(uint32_t addr, uint32_t lo, uint32_t hi) {
    asm volatile("st.shared.v2.u32 [%0], {%1, %2};" :: "r"(addr), "r"(lo), "r"(hi) : "memory");
}

// ---------------- per-batch bias: c[b] = b1 + new_nodes[b] @ W1[128:256] ----------------
__device__ float g_cbias[BATCH * 256];

__global__ void cbias_kernel(const float* __restrict__ new_nodes,
                             const float* __restrict__ W1,
                             const float* __restrict__ b1) {
    int b = blockIdx.x;
    int n = threadIdx.x;
    float acc = b1[n];
    const float* nb = new_nodes + (size_t)b * HID;
#pragma unroll 8
    for (int f = 0; f < HID; ++f)
        acc = fmaf(nb[f], W1[(size_t)(HID + f) * 256 + n], acc);
    g_cbias[b * 256 + n] = acc;
}

// ---------------- main fused kernel ----------------
__global__ void __launch_bounds__(256, 1)
edge_mlp_kernel(const float* __restrict__ nodes,   // [NROWS,128]
                const float* __restrict__ W1,      // [256,256]
                const float* __restrict__ W2,      // [256,64]
                const float* __restrict__ W3,      // [64]
                const float* __restrict__ b2,      // [64]
                const float* __restrict__ b3,      // [1]
                float* __restrict__ out)           // [NROWS]
{
    extern __shared__ char smem[];
    const uint32_t sb = s2u(smem);
    const int tid  = threadIdx.x;
    const int wid  = tid >> 5;
    const int lane = tid & 31;
    const int l7   = lane & 7;
    const int l3   = lane & 3;
    const int rsel = (lane >> 3) & 1;   // row-half selector for ldmatrix
    const int usub = lane >> 4;         // k-unit selector for ldmatrix
    const int g    = tid >> 7;          // group 0: warps 0-3 (rows 0-127); group 1: warps 4-7
    const int gtid = tid & 127;

    float* w3_s = reinterpret_cast<float*>(smem + OFF_W3);
    float* b2_s = reinterpret_cast<float*>(smem + OFF_B2C);
    float* b3_s = reinterpret_cast<float*>(smem + OFF_B3);
    float* cs_g = reinterpret_cast<float*>(smem + OFF_CS) + g * 256;
    float* stg  = reinterpret_cast<float*>(smem + OFF_STG);

    const uint32_t sbar = sb + OFF_BAR;

    if (tid == 0) mbar_init(sbar, 1);
    __syncthreads();

    // load 0: tile blockIdx.x, rows [0,128) — issued ASAP, overlaps weight conversion
    if (tid == 0) {
        mbar_expect(sbar, 65536);
        bulk_g2s(sb + OFF_STG, nodes + (size_t)blockIdx.x * (256 * HID), 65536, sbar);
    }

    // small constants
    if (tid < 64) { w3_s[tid] = W3[tid]; b2_s[tid] = b2[tid]; }
    if (tid == 0) b3_s[0] = b3[0];

    // B1: [n=256][k=128] f16, 256B rows, XOR swizzle (unit16B ^ row&7). B1[n][k]=W1[k*256+n]
    {
        const int n = tid;
#pragma unroll 4
        for (int kp = 0; kp < 64; ++kp) {
            float a = W1[(size_t)(2 * kp) * 256 + n];
            float b = W1[(size_t)(2 * kp + 1) * 256 + n];
            uint32_t addr = (uint32_t)(n * 256 + (((kp >> 2) ^ (n & 7)) << 4) + (kp & 3) * 4);
            *reinterpret_cast<uint32_t*>(smem + OFF_B1 + addr) = pack2(a, b);
        }
    }
    // B2: [n=64][k=256] f16, 512B rows, same swizzle. B2[n][k]=W2[k*64+n]
    {
#pragma unroll 4
        for (int j = 0; j < 32; ++j) {
            int idx = tid + j * 256;
            int n  = idx & 63;
            int kp = idx >> 6;              // 0..127
            float a = W2[(size_t)(2 * kp) * 64 + n];
            float b = W2[(size_t)(2 * kp + 1) * 64 + n];
            uint32_t addr = (uint32_t)(n * 512 + (((kp >> 2) ^ (n & 7)) << 4) + (kp & 3) * 4);
            *reinterpret_cast<uint32_t*>(smem + OFF_B2 + addr) = pack2(a, b);
        }
    }
    __syncthreads();
    // after this point: NO full-CTA barriers; the two groups run decoupled.

    // per-warp ldmatrix lane bases
    const uint32_t aBase0 = sb + OFF_A1 + (uint32_t)((wid * 32      + l7 + (rsel << 3)) * 256);
    const uint32_t aBase1 = sb + OFF_A1 + (uint32_t)((wid * 32 + 16 + l7 + (rsel << 3)) * 256);
    const uint32_t b1LaneBase = sb + OFF_B1 + (uint32_t)((l7 + (rsel << 3)) * 256);
    const uint32_t b2LaneBase = sb + OFF_B2 + (uint32_t)((l7 + (rsel << 3)) * 512);

    const int grid = gridDim.x;

    for (int t = blockIdx.x; t < NT2; t += grid) {
        // ---- wait my group's staged half (parity == g by construction) ----
        mbar_wait(sbar, (uint32_t)g);

        // per-tile bias into group-private copy (batch constant across the tile)
        const int b = t >> 4;
        cs_g[gtid]       = g_cbias[b * 256 + gtid];
        cs_g[gtid + 128] = g_cbias[b * 256 + 128 + gtid];

        // ---- convert stage fp32 -> f16 swizzled A1 rows [g*128, g*128+128) ----
        // two k-pairs per iteration: float4 load + STS.64 (same 16B swizzle unit)
#pragma unroll 4
        for (int j = 0; j < 32; ++j) {
            int idx = gtid + j * 128;                // 0..4095
            int m   = idx >> 5;                      // local row 0..127
            int kp2 = idx & 31;                      // pair-of-pairs 0..31
            float4 v = reinterpret_cast<const float4*>(stg)[m * 32 + kp2];
            uint32_t lo = pack2(v.x, v.y);
            uint32_t hi = pack2(v.z, v.w);
            int kp = kp2 * 2;
            uint32_t addr = sb + OFF_A1 +
                (uint32_t)((g * 128 + m) * 256 + (((kp >> 2) ^ (m & 7)) << 4) + (kp & 3) * 4);
            sts64(addr, lo, hi);
        }
        named_bar(1 + g);

        // ---- group leader issues the NEXT load (stage buffer now free) ----
        if (gtid == 0) {
            if (g == 0) {
                mbar_expect(sbar, 65536);
                bulk_g2s(sb + OFF_STG, nodes + ((size_t)t * 256 + 128) * HID, 65536, sbar);
            } else if (t + grid < NT2) {
                mbar_expect(sbar, 65536);
                bulk_g2s(sb + OFF_STG, nodes + (size_t)(t + grid) * 256 * HID, 65536, sbar);
            }
        }

        // ---- load A fragments: 32 rows x 128 k -> 2 halves x 8 k-steps ----
        uint32_t areg[2][8][4];
#pragma unroll
        for (int s = 0; s < 8; ++s) {
            ldsm4(areg[0][s], aBase0 + (uint32_t)((((s << 1) + usub) ^ l7) << 4));
            ldsm4(areg[1][s], aBase1 + (uint32_t)((((s << 1) + usub) ^ l7) << 4));
        }

        float c2[2][8][4];
#pragma unroll
        for (int h = 0; h < 2; ++h)
#pragma unroll
            for (int f = 0; f < 8; ++f)
#pragma unroll
                for (int q = 0; q < 4; ++q) c2[h][f][q] = 0.f;

        // ---- fused layers 1+2, p = 16-col block of layer-1 output (rolled, SW-pipelined) ----
        for (int p = 0; p < 16; ++p) {
            float c1[2][2][4];
#pragma unroll
            for (int h = 0; h < 2; ++h)
#pragma unroll
                for (int n = 0; n < 2; ++n)
#pragma unroll
                    for (int q = 0; q < 4; ++q) c1[h][n][q] = 0.f;

            const uint32_t bB = b1LaneBase + (uint32_t)(p * 16 * 256);

            // software-pipelined B1 fetch: br for step s+1 issues before MMAs of step s
            uint32_t brc[4];
            ldsm4(brc, bB + (uint32_t)((usub ^ l7) << 4));
#pragma unroll
            for (int s = 0; s < 8; ++s) {
                uint32_t brn[4];
                if (s < 7)
                    ldsm4(brn, bB + (uint32_t)(((((s + 1) << 1) + usub) ^ l7) << 4));
                mma16816(c1[0][0], areg[0][s], brc[0], brc[2]);
                mma16816(c1[0][1], areg[0][s], brc[1], brc[3]);
                mma16816(c1[1][0], areg[1][s], brc[0], brc[2]);
                mma16816(c1[1][1], areg[1][s], brc[1], brc[3]);
                if (s < 7) {
                    brc[0] = brn[0]; brc[1] = brn[1]; brc[2] = brn[2]; brc[3] = brn[3];
                }
            }

            // prefetch first layer-2 B fragment (independent of pack below)
            const uint32_t koff = (uint32_t)((((p << 1) + usub) ^ l7) << 4);
            uint32_t br2c[4];
            ldsm4(br2c, b2LaneBase + koff);

            // epilogue-1 in registers: relu(+c) -> pack f16 -> layer-2 A frags
            float2 cva = *reinterpret_cast<const float2*>(&cs_g[p * 16 + l3 * 2]);
            float2 cvb = *reinterpret_cast<const float2*>(&cs_g[p * 16 + 8 + l3 * 2]);
            uint32_t a2[2][4];
#pragma unroll
            for (int h = 0; h < 2; ++h) {
                a2[h][0] = pack2(fmaxf(c1[h][0][0] + cva.x, 0.f), fmaxf(c1[h][0][1] + cva.y, 0.f));
                a2[h][1] = pack2(fmaxf(c1[h][0][2] + cva.x, 0.f), fmaxf(c1[h][0][3] + cva.y, 0.f));
                a2[h][2] = pack2(fmaxf(c1[h][1][0] + cvb.x, 0.f), fmaxf(c1[h][1][1] + cvb.y, 0.f));
                a2[h][3] = pack2(fmaxf(c1[h][1][2] + cvb.x, 0.f), fmaxf(c1[h][1][3] + cvb.y, 0.f));
            }

            // layer-2 partial: k-step p, software-pipelined B2 fetch
#pragma unroll
            for (int p2 = 0; p2 < 4; ++p2) {
                uint32_t br2n[4];
                if (p2 < 3)
                    ldsm4(br2n, b2LaneBase + (uint32_t)((p2 + 1) * 16 * 512) + koff);
                mma16816(c2[0][2 * p2],     a2[0], br2c[0], br2c[2]);
                mma16816(c2[0][2 * p2 + 1], a2[0], br2c[1], br2c[3]);
                mma16816(c2[1][2 * p2],     a2[1], br2c[0], br2c[2]);
                mma16816(c2[1][2 * p2 + 1], a2[1], br2c[1], br2c[3]);
                if (p2 < 3) {
                    br2c[0] = br2n[0]; br2c[1] = br2n[1]; br2c[2] = br2n[2]; br2c[3] = br2n[3];
                }
            }
        }

        // ---- epilogue 2: relu(C2 + b2) . W3 + b3 -> sigmoid -> out ----
        const float bias3 = b3_s[0];
#pragma unroll
        for (int h = 0; h < 2; ++h) {
            float accl = 0.f, acch = 0.f;
#pragma unroll
            for (int f2 = 0; f2 < 8; ++f2) {
                const int col = f2 * 8 + l3 * 2;
                float w0 = w3_s[col], w1 = w3_s[col + 1];
                float bb0 = b2_s[col], bb1 = b2_s[col + 1];
                accl = fmaf(fmaxf(c2[h][f2][0] + bb0, 0.f), w0, accl);
                accl = fmaf(fmaxf(c2[h][f2][1] + bb1, 0.f), w1, accl);
                acch = fmaf(fmaxf(c2[h][f2][2] + bb0, 0.f), w0, acch);
                acch = fmaf(fmaxf(c2[h][f2][3] + bb1, 0.f), w1, acch);
            }
            accl += __shfl_xor_sync(0xffffffffu, accl, 1);
            accl += __shfl_xor_sync(0xffffffffu, accl, 2);
            acch += __shfl_xor_sync(0xffffffffu, acch, 1);
            acch += __shfl_xor_sync(0xffffffffu, acch, 2);
            if (l3 == 0) {
                const int row = t * 256 + wid * 32 + 16 * h + (lane >> 2);
                out[row]     = 1.f / (1.f + __expf(-(accl + bias3)));
                out[row + 8] = 1.f / (1.f + __expf(-(acch + bias3)));
            }
        }

        named_bar(1 + g);   // protect cs_g (and ordering) for the next iteration
    }
}

// ---------------- launch ----------------
extern "C" void kernel_launch(void* const* d_in, const int* in_sizes, int n_in,
                              void* d_out, int out_size) {
    const float* nodes = (const float*)d_in[0];   // [128,4096,128]
    const float* newn  = (const float*)d_in[1];   // [128,1,128]
    const float* W1    = (const float*)d_in[2];   // [256,256]
    const float* b1    = (const float*)d_in[3];   // [256]
    const float* W2    = (const float*)d_in[4];   // [256,64]
    const float* b2    = (const float*)d_in[5];   // [64]
    const float* W3    = (const float*)d_in[6];   // [64,1]
    const float* b3    = (const float*)d_in[7];   // [1]
    float* out = (float*)d_out;

    (void)in_sizes; (void)n_in; (void)out_size;

    cudaFuncSetAttribute(edge_mlp_kernel,
                         cudaFuncAttributeMaxDynamicSharedMemorySize, SMEM_BYTES);

    int nsm = 148;
    cudaDeviceGetAttribute(&nsm, cudaDevAttrMultiProcessorCount, 0);
    if (nsm <= 0) nsm = 148;
    if (nsm > NT2) nsm = NT2;

    cbias_kernel<<<BATCH, 256>>>(newn, W1, b1);
    edge_mlp_kernel<<<nsm, 256, SMEM_BYTES>>>(nodes, W1, W2, W3, b2, b3, out);
}

// round 7
// speedup vs baseline: 1.1696x; 1.0249x over previous
#include <cuda_runtime.h>
#include <cuda_fp16.h>
#include <cstdint>

#define DEV __device__ __forceinline__

// ---------------- problem constants ----------------
static constexpr int HID    = 128;
static constexpr int BATCH  = 128;
static constexpr int NROWS  = 128 * 4096;     // 524288
static constexpr int NT2    = NROWS / 256;    // 2048 tiles of 256 rows

// ---------------- SMEM layout (byte offsets) ----------------
static constexpr int OFF_BAR  = 0;                  // mbarrier (8B)
static constexpr int OFF_W3   = 64;                 // 64 f32
static constexpr int OFF_B2C  = 320;                // 64 f32
static constexpr int OFF_B3   = 576;                // 1 f32
static constexpr int OFF_CS   = 1024;               // [2][256] f32 (2KB)
static constexpr int OFF_A1   = 3072;               // 256 x 128 f16 swizzled (64KB)
static constexpr int OFF_B1   = OFF_A1 + 65536;     // 256n x 128k f16 swizzled (64KB)
static constexpr int OFF_B2   = OFF_B1 + 65536;     // 64n x 256k f16 swizzled (32KB)
static constexpr int OFF_STG  = OFF_B2 + 32768;     // fp32 stage: 128 rows x 128 (64KB)
static constexpr int SMEM_BYTES = OFF_STG + 65536;  // 232448 == opt-in max

// ---------------- helpers ----------------
DEV uint32_t s2u(const void* p) {
    uint32_t a;
    asm("{ .reg .u64 t; cvta.to.shared.u64 t, %1; cvt.u32.u64 %0, t; }" : "=r"(a) : "l"(p));
    return a;
}
DEV uint32_t pack2(float a, float b) {
    __half2 h = __floats2half2_rn(a, b);
    return *reinterpret_cast<uint32_t*>(&h);
}
DEV void mbar_init(uint32_t mbar, uint32_t cnt) {
    asm volatile("mbarrier.init.shared.b64 [%0], %1;" :: "r"(mbar), "r"(cnt) : "memory");
}
DEV void mbar_expect(uint32_t mbar, uint32_t bytes) {
    asm volatile("mbarrier.arrive.expect_tx.shared.b64 _, [%0], %1;" :: "r"(mbar), "r"(bytes) : "memory");
}
DEV void mbar_wait(uint32_t mbar, uint32_t parity) {
    asm volatile(
        "{\n\t.reg .pred P;\n\t"
        "LW%=:\n\t"
        "mbarrier.try_wait.parity.acquire.cta.shared::cta.b64 P, [%0], %1, 0x989680;\n\t"
        "@P bra LD%=;\n\t"
        "bra LW%=;\n\t"
        "LD%=:\n\t}"
        :: "r"(mbar), "r"(parity) : "memory");
}
DEV void bulk_g2s(uint32_t dst, const void* src, uint32_t bytes, uint32_t mbar) {
    asm volatile(
        "cp.async.bulk.shared::cta.global.mbarrier::complete_tx::bytes [%0], [%1], %2, [%3];"
        :: "r"(dst), "l"(src), "r"(bytes), "r"(mbar) : "memory");
}
DEV void ldsm4(uint32_t* r, uint32_t addr) {
    asm volatile("ldmatrix.sync.aligned.m8n8.x4.shared.b16 {%0,%1,%2,%3}, [%4];"
        : "=r"(r[0]), "=r"(r[1]), "=r"(r[2]), "=r"(r[3]) : "r"(addr));
}
DEV void mma16816(float* c, const uint32_t* a, uint32_t b0, uint32_t b1) {
    asm volatile(
        "mma.sync.aligned.m16n8k16.row.col.f32.f16.f16.f32 "
        "{%0,%1,%2,%3}, {%4,%5,%6,%7}, {%8,%9}, {%0,%1,%2,%3};"
        : "+f"(c[0]), "+f"(c[1]), "+f"(c[2]), "+f"(c[3])
        : "r"(a[0]), "r"(a[1]), "r"(a[2]), "r"(a[3]), "r"(b0), "r"(b1));
}
DEV void named_bar(int id) {
    asm volatile("bar.sync %0, 128;" :: "r"(id) : "memory");
}
DEV void sts128(uint32_t addr, uint32_t a, uint32_t b, uint32_t c, uint32_t d) {
    asm volatile("st.shared.v4.u32 [%0], {%1, %2, %3, %4};"
        :: "r"(addr), "r"(a), "r"(b), "r"(c), "r"(d) : "memory");
}

// ---------------- per-batch bias: c[b] = b1 + new_nodes[b] @ W1[128:256] ----------------
__device__ float g_cbias[BATCH * 256];

__global__ void cbias_kernel(const float* __restrict__ new_nodes,
                             const float* __restrict__ W1,
                             const float* __restrict__ b1) {
    int b = blockIdx.x;
    int n = threadIdx.x;
    float acc = b1[n];
    const float* nb = new_nodes + (size_t)b * HID;
#pragma unroll 8
    for (int f = 0; f < HID; ++f)
        acc = fmaf(nb[f], W1[(size_t)(HID + f) * 256 + n], acc);
    g_cbias[b * 256 + n] = acc;
}

// ---------------- main fused kernel ----------------
__global__ void __launch_bounds__(256, 1)
edge_mlp_kernel(const float* __restrict__ nodes,   // [NROWS,128]
                const float* __restrict__ W1,      // [256,256]
                const float* __restrict__ W2,      // [256,64]
                const float* __restrict__ W3,      // [64]
                const float* __restrict__ b2,      // [64]
                const float* __restrict__ b3,      // [1]
                float* __restrict__ out)           // [NROWS]
{
    extern __shared__ char smem[];
    const uint32_t sb = s2u(smem);
    const int tid  = threadIdx.x;
    const int wid  = tid >> 5;
    const int lane = tid & 31;
    const int l7   = lane & 7;
    const int l3   = lane & 3;
    const int rsel = (lane >> 3) & 1;   // row-half selector for ldmatrix
    const int usub = lane >> 4;         // k-unit selector for ldmatrix
    const int g    = tid >> 7;          // group 0: warps 0-3 (rows 0-127); group 1: warps 4-7
    const int gtid = tid & 127;

    float* w3_s = reinterpret_cast<float*>(smem + OFF_W3);
    float* b2_s = reinterpret_cast<float*>(smem + OFF_B2C);
    float* b3_s = reinterpret_cast<float*>(smem + OFF_B3);
    float* cs_g = reinterpret_cast<float*>(smem + OFF_CS) + g * 256;
    float* stg  = reinterpret_cast<float*>(smem + OFF_STG);

    const uint32_t sbar = sb + OFF_BAR;

    if (tid == 0) mbar_init(sbar, 1);
    __syncthreads();

    // load 0: tile blockIdx.x, rows [0,128) — issued ASAP, overlaps weight conversion
    if (tid == 0) {
        mbar_expect(sbar, 65536);
        bulk_g2s(sb + OFF_STG, nodes + (size_t)blockIdx.x * (256 * HID), 65536, sbar);
    }

    // small constants
    if (tid < 64) { w3_s[tid] = W3[tid]; b2_s[tid] = b2[tid]; }
    if (tid == 0) b3_s[0] = b3[0];

    // B1: [n=256][k=128] f16, 256B rows, XOR swizzle (unit16B ^ row&7). B1[n][k]=W1[k*256+n]
    {
        const int n = tid;
#pragma unroll 4
        for (int kp = 0; kp < 64; ++kp) {
            float a = W1[(size_t)(2 * kp) * 256 + n];
            float b = W1[(size_t)(2 * kp + 1) * 256 + n];
            uint32_t addr = (uint32_t)(n * 256 + (((kp >> 2) ^ (n & 7)) << 4) + (kp & 3) * 4);
            *reinterpret_cast<uint32_t*>(smem + OFF_B1 + addr) = pack2(a, b);
        }
    }
    // B2: [n=64][k=256] f16, 512B rows, same swizzle. B2[n][k]=W2[k*64+n]
    {
#pragma unroll 4
        for (int j = 0; j < 32; ++j) {
            int idx = tid + j * 256;
            int n  = idx & 63;
            int kp = idx >> 6;              // 0..127
            float a = W2[(size_t)(2 * kp) * 64 + n];
            float b = W2[(size_t)(2 * kp + 1) * 64 + n];
            uint32_t addr = (uint32_t)(n * 512 + (((kp >> 2) ^ (n & 7)) << 4) + (kp & 3) * 4);
            *reinterpret_cast<uint32_t*>(smem + OFF_B2 + addr) = pack2(a, b);
        }
    }
    __syncthreads();
    // after this point: NO full-CTA barriers; the two groups run decoupled.

    // per-warp ldmatrix lane bases
    const uint32_t aBase0 = sb + OFF_A1 + (uint32_t)((wid * 32      + l7 + (rsel << 3)) * 256);
    const uint32_t aBase1 = sb + OFF_A1 + (uint32_t)((wid * 32 + 16 + l7 + (rsel << 3)) * 256);
    const uint32_t b1LaneBase = sb + OFF_B1 + (uint32_t)((l7 + (rsel << 3)) * 256);
    const uint32_t b2LaneBase = sb + OFF_B2 + (uint32_t)((l7 + (rsel << 3)) * 512);

    const int grid = gridDim.x;

    for (int t = blockIdx.x; t < NT2; t += grid) {
        // ---- prefetch per-tile bias into regs BEFORE waiting (hides LDG latency) ----
        const int b = t >> 4;
        const float cb0 = g_cbias[b * 256 + gtid];
        const float cb1 = g_cbias[b * 256 + 128 + gtid];

        // ---- wait my group's staged half (parity == g by construction) ----
        mbar_wait(sbar, (uint32_t)g);

        cs_g[gtid]       = cb0;
        cs_g[gtid + 128] = cb1;

        // ---- convert stage fp32 -> f16 swizzled A1 rows [g*128, g*128+128) ----
        // one 16B swizzle unit per iteration: 2x float4 load + STS.128
#pragma unroll 4
        for (int j = 0; j < 16; ++j) {
            int idx = gtid + j * 128;                // 0..2047
            int m   = idx >> 4;                      // local row 0..127
            int u   = idx & 15;                      // 16B unit 0..15
            float4 v0 = reinterpret_cast<const float4*>(stg)[m * 32 + u * 2];
            float4 v1 = reinterpret_cast<const float4*>(stg)[m * 32 + u * 2 + 1];
            uint32_t addr = sb + OFF_A1 +
                (uint32_t)((g * 128 + m) * 256 + ((u ^ (m & 7)) << 4));
            sts128(addr, pack2(v0.x, v0.y), pack2(v0.z, v0.w),
                         pack2(v1.x, v1.y), pack2(v1.z, v1.w));
        }
        named_bar(1 + g);

        // ---- group leader issues the NEXT load (stage buffer now free) ----
        if (gtid == 0) {
            if (g == 0) {
                mbar_expect(sbar, 65536);
                bulk_g2s(sb + OFF_STG, nodes + ((size_t)t * 256 + 128) * HID, 65536, sbar);
            } else if (t + grid < NT2) {
                mbar_expect(sbar, 65536);
                bulk_g2s(sb + OFF_STG, nodes + (size_t)(t + grid) * 256 * HID, 65536, sbar);
            }
        }

        // ---- load A fragments: 32 rows x 128 k -> 2 halves x 8 k-steps ----
        uint32_t areg[2][8][4];
#pragma unroll
        for (int s = 0; s < 8; ++s) {
            ldsm4(areg[0][s], aBase0 + (uint32_t)((((s << 1) + usub) ^ l7) << 4));
            ldsm4(areg[1][s], aBase1 + (uint32_t)((((s << 1) + usub) ^ l7) << 4));
        }

        float c2[2][8][4];
#pragma unroll
        for (int h = 0; h < 2; ++h)
#pragma unroll
            for (int f = 0; f < 8; ++f)
#pragma unroll
                for (int q = 0; q < 4; ++q) c2[h][f][q] = 0.f;

        // ---- fused layers 1+2, TWO 16-col blocks of layer-1 output per iter ----
        for (int pp = 0; pp < 8; ++pp) {
            const int p0 = 2 * pp;
            float c1[2][2][2][4];   // [pblk][h][n][q]
#pragma unroll
            for (int pb = 0; pb < 2; ++pb)
#pragma unroll
                for (int h = 0; h < 2; ++h)
#pragma unroll
                    for (int n = 0; n < 2; ++n)
#pragma unroll
                        for (int q = 0; q < 4; ++q) c1[pb][h][n][q] = 0.f;

            const uint32_t bB0 = b1LaneBase + (uint32_t)(p0 * 16 * 256);
            const uint32_t bB1 = bB0 + 4096;

            // prefetch stream0 s=0
            uint32_t brc0[4];
            ldsm4(brc0, bB0 + (uint32_t)((usub ^ l7) << 4));
#pragma unroll
            for (int s = 0; s < 8; ++s) {
                const uint32_t soff = (uint32_t)((((s << 1) + usub) ^ l7) << 4);
                // stream1 B for this step (hidden by stream0 MMAs below)
                uint32_t br1[4];
                ldsm4(br1, bB1 + soff);
                // stream0 MMAs (brc0 ready)
                mma16816(c1[0][0][0], areg[0][s], brc0[0], brc0[2]);
                mma16816(c1[0][0][1], areg[0][s], brc0[1], brc0[3]);
                mma16816(c1[0][1][0], areg[1][s], brc0[0], brc0[2]);
                mma16816(c1[0][1][1], areg[1][s], brc0[1], brc0[3]);
                // prefetch stream0 next step
                uint32_t brn0[4];
                if (s < 7)
                    ldsm4(brn0, bB0 + (uint32_t)(((((s + 1) << 1) + usub) ^ l7) << 4));
                // stream1 MMAs (br1 ready: 4 MMAs of latency cover)
                mma16816(c1[1][0][0], areg[0][s], br1[0], br1[2]);
                mma16816(c1[1][0][1], areg[0][s], br1[1], br1[3]);
                mma16816(c1[1][1][0], areg[1][s], br1[0], br1[2]);
                mma16816(c1[1][1][1], areg[1][s], br1[1], br1[3]);
                if (s < 7) {
                    brc0[0] = brn0[0]; brc0[1] = brn0[1]; brc0[2] = brn0[2]; brc0[3] = brn0[3];
                }
            }

            const uint32_t koffA = (uint32_t)((((p0 << 1) + usub) ^ l7) << 4);
            const uint32_t koffB = (uint32_t)(((((p0 + 1) << 1) + usub) ^ l7) << 4);

            // prefetch first layer-2 B fragment for stream A (hidden by pack below)
            uint32_t br2a[4];
            ldsm4(br2a, b2LaneBase + koffA);

            // epilogue-1 in registers: relu(+c) -> pack f16 -> layer-2 A frags
            uint32_t a2[2][2][4];   // [pblk][h]
#pragma unroll
            for (int pb = 0; pb < 2; ++pb) {
                const int pc = (p0 + pb) * 16;
                float2 cva = *reinterpret_cast<const float2*>(&cs_g[pc + l3 * 2]);
                float2 cvb = *reinterpret_cast<const float2*>(&cs_g[pc + 8 + l3 * 2]);
#pragma unroll
                for (int h = 0; h < 2; ++h) {
                    a2[pb][h][0] = pack2(fmaxf(c1[pb][h][0][0] + cva.x, 0.f), fmaxf(c1[pb][h][0][1] + cva.y, 0.f));
                    a2[pb][h][1] = pack2(fmaxf(c1[pb][h][0][2] + cva.x, 0.f), fmaxf(c1[pb][h][0][3] + cva.y, 0.f));
                    a2[pb][h][2] = pack2(fmaxf(c1[pb][h][1][0] + cvb.x, 0.f), fmaxf(c1[pb][h][1][1] + cvb.y, 0.f));
                    a2[pb][h][3] = pack2(fmaxf(c1[pb][h][1][2] + cvb.x, 0.f), fmaxf(c1[pb][h][1][3] + cvb.y, 0.f));
                }
            }

            // layer-2 partial: k-steps p0, p0+1; SW-pipelined B2 fetches
#pragma unroll
            for (int p2 = 0; p2 < 4; ++p2) {
                const uint32_t rowOff = (uint32_t)(p2 * 16 * 512);
                uint32_t br2b[4];
                ldsm4(br2b, b2LaneBase + rowOff + koffB);
                uint32_t br2an[4];
                if (p2 < 3)
                    ldsm4(br2an, b2LaneBase + (uint32_t)((p2 + 1) * 16 * 512) + koffA);
                // stream A MMAs (br2a ready)
                mma16816(c2[0][2 * p2],     a2[0][0], br2a[0], br2a[2]);
                mma16816(c2[0][2 * p2 + 1], a2[0][0], br2a[1], br2a[3]);
                mma16816(c2[1][2 * p2],     a2[0][1], br2a[0], br2a[2]);
                mma16816(c2[1][2 * p2 + 1], a2[0][1], br2a[1], br2a[3]);
                // stream B MMAs (br2b ready after A's 4 MMAs)
                mma16816(c2[0][2 * p2],     a2[1][0], br2b[0], br2b[2]);
                mma16816(c2[0][2 * p2 + 1], a2[1][0], br2b[1], br2b[3]);
                mma16816(c2[1][2 * p2],     a2[1][1], br2b[0], br2b[2]);
                mma16816(c2[1][2 * p2 + 1], a2[1][1], br2b[1], br2b[3]);
                if (p2 < 3) {
                    br2a[0] = br2an[0]; br2a[1] = br2an[1]; br2a[2] = br2an[2]; br2a[3] = br2an[3];
                }
            }
        }

        // ---- epilogue 2: relu(C2 + b2) . W3 + b3 -> sigmoid -> out ----
        const float bias3 = b3_s[0];
#pragma unroll
        for (int h = 0; h < 2; ++h) {
            float accl = 0.f, acch = 0.f;
#pragma unroll
            for (int f2 = 0; f2 < 8; ++f2) {
                const int col = f2 * 8 + l3 * 2;
                float w0 = w3_s[col], w1 = w3_s[col + 1];
                float bb0 = b2_s[col], bb1 = b2_s[col + 1];
                accl = fmaf(fmaxf(c2[h][f2][0] + bb0, 0.f), w0, accl);
                accl = fmaf(fmaxf(c2[h][f2][1] + bb1, 0.f), w1, accl);
                acch = fmaf(fmaxf(c2[h][f2][2] + bb0, 0.f), w0, acch);
                acch = fmaf(fmaxf(c2[h][f2][3] + bb1, 0.f), w1, acch);
            }
            accl += __shfl_xor_sync(0xffffffffu, accl, 1);
            accl += __shfl_xor_sync(0xffffffffu, accl, 2);
            acch += __shfl_xor_sync(0xffffffffu, acch, 1);
            acch += __shfl_xor_sync(0xffffffffu, acch, 2);
            if (l3 == 0) {
                const int row = t * 256 + wid * 32 + 16 * h + (lane >> 2);
                out[row]     = 1.f / (1.f + __expf(-(accl + bias3)));
                out[row + 8] = 1.f / (1.f + __expf(-(acch + bias3)));
            }
        }

        named_bar(1 + g);   // protect cs_g (and ordering) for the next iteration
    }
}

// ---------------- launch ----------------
extern "C" void kernel_launch(void* const* d_in, const int* in_sizes, int n_in,
                              void* d_out, int out_size) {
    const float* nodes = (const float*)d_in[0];   // [128,4096,128]
    const float* newn  = (const float*)d_in[1];   // [128,1,128]
    const float* W1    = (const float*)d_in[2];   // [256,256]
    const float* b1    = (const float*)d_in[3];   // [256]
    const float* W2    = (const float*)d_in[4];   // [256,64]
    const float* b2    = (const float*)d_in[5];   // [64]
    const float* W3    = (const float*)d_in[6];   // [64,1]
    const float* b3    = (const float*)d_in[7];   // [1]
    float* out = (float*)d_out;

    (void)in_sizes; (void)n_in; (void)out_size;

    cudaFuncSetAttribute(edge_mlp_kernel,
                         cudaFuncAttributeMaxDynamicSharedMemorySize, SMEM_BYTES);

    int nsm = 148;
    cudaDeviceGetAttribute(&nsm, cudaDevAttrMultiProcessorCount, 0);
    if (nsm <= 0) nsm = 148;
    if (nsm > NT2) nsm = NT2;

    cbias_kernel<<<BATCH, 256>>>(newn, W1, b1);
    edge_mlp_kernel<<<nsm, 256, SMEM_BYTES>>>(nodes, W1, W2, W3, b2, b3, out);
}

// round 8
// speedup vs baseline: 1.2286x; 1.0504x over previous
#include <cuda_runtime.h>
#include <cuda_fp16.h>
#include <cstdint>

#define DEV __device__ __forceinline__

// ---------------- problem constants ----------------
static constexpr int HID    = 128;
static constexpr int BATCH  = 128;
static constexpr int NROWS  = 128 * 4096;     // 524288
static constexpr int NT2    = NROWS / 256;    // 2048 tiles of 256 rows

// ---------------- SMEM layout (byte offsets) ----------------
static constexpr int OFF_BAR  = 0;                  // mbarrier (8B)
static constexpr int OFF_W3   = 64;                 // 64 f32
static constexpr int OFF_B2C  = 320;                // 64 f32
static constexpr int OFF_B3   = 576;                // 1 f32
static constexpr int OFF_CS   = 1024;               // [2][128] half2 bias (1KB)
static constexpr int OFF_A1   = 3072;               // 256 x 128 f16 swizzled (64KB)
static constexpr int OFF_B1   = OFF_A1 + 65536;     // 256n x 128k f16 swizzled (64KB)
static constexpr int OFF_B2   = OFF_B1 + 65536;     // 64n x 256k f16 swizzled (32KB)
static constexpr int OFF_STG  = OFF_B2 + 32768;     // fp32 stage: 128 rows x 128 (64KB)
static constexpr int SMEM_BYTES = OFF_STG + 65536;  // 232448 == opt-in max

// ---------------- helpers ----------------
DEV uint32_t s2u(const void* p) {
    uint32_t a;
    asm("{ .reg .u64 t; cvta.to.shared.u64 t, %1; cvt.u32.u64 %0, t; }" : "=r"(a) : "l"(p));
    return a;
}
DEV uint32_t pack2(float a, float b) {
    __half2 h = __floats2half2_rn(a, b);
    return *reinterpret_cast<uint32_t*>(&h);
}
DEV uint32_t hadd2_relu(uint32_t x, uint32_t bias) {
    __half2 v = __hadd2(*reinterpret_cast<__half2*>(&x),
                        *reinterpret_cast<__half2*>(&bias));
    __half2 z = __floats2half2_rn(0.f, 0.f);
    __half2 r = __hmax2(v, z);
    return *reinterpret_cast<uint32_t*>(&r);
}
DEV void mbar_init(uint32_t mbar, uint32_t cnt) {
    asm volatile("mbarrier.init.shared.b64 [%0], %1;" :: "r"(mbar), "r"(cnt) : "memory");
}
DEV void mbar_expect(uint32_t mbar, uint32_t bytes) {
    asm volatile("mbarrier.arrive.expect_tx.shared.b64 _, [%0], %1;" :: "r"(mbar), "r"(bytes) : "memory");
}
DEV void mbar_wait(uint32_t mbar, uint32_t parity) {
    asm volatile(
        "{\n\t.reg .pred P;\n\t"
        "LW%=:\n\t"
        "mbarrier.try_wait.parity.acquire.cta.shared::cta.b64 P, [%0], %1, 0x989680;\n\t"
        "@P bra LD%=;\n\t"
        "bra LW%=;\n\t"
        "LD%=:\n\t}"
        :: "r"(mbar), "r"(parity) : "memory");
}
DEV void bulk_g2s(uint32_t dst, const void* src, uint32_t bytes, uint32_t mbar) {
    asm volatile(
        "cp.async.bulk.shared::cta.global.mbarrier::complete_tx::bytes [%0], [%1], %2, [%3];"
        :: "r"(dst), "l"(src), "r"(bytes), "r"(mbar) : "memory");
}
DEV void ldsm4(uint32_t* r, uint32_t addr) {
    asm volatile("ldmatrix.sync.aligned.m8n8.x4.shared.b16 {%0,%1,%2,%3}, [%4];"
        : "=r"(r[0]), "=r"(r[1]), "=r"(r[2]), "=r"(r[3]) : "r"(addr));
}
// f32-accumulate MMA (layer 2)
DEV void mma16816(float* c, const uint32_t* a, uint32_t b0, uint32_t b1) {
    asm volatile(
        "mma.sync.aligned.m16n8k16.row.col.f32.f16.f16.f32 "
        "{%0,%1,%2,%3}, {%4,%5,%6,%7}, {%8,%9}, {%0,%1,%2,%3};"
        : "+f"(c[0]), "+f"(c[1]), "+f"(c[2]), "+f"(c[3])
        : "r"(a[0]), "r"(a[1]), "r"(a[2]), "r"(a[3]), "r"(b0), "r"(b1));
}
// f16-accumulate MMA (layer 1) — D fragment is A-fragment-layout compatible
DEV void mma16816h(uint32_t* c, const uint32_t* a, uint32_t b0, uint32_t b1) {
    asm volatile(
        "mma.sync.aligned.m16n8k16.row.col.f16.f16.f16.f16 "
        "{%0,%1}, {%2,%3,%4,%5}, {%6,%7}, {%0,%1};"
        : "+r"(c[0]), "+r"(c[1])
        : "r"(a[0]), "r"(a[1]), "r"(a[2]), "r"(a[3]), "r"(b0), "r"(b1));
}
DEV void named_bar(int id) {
    asm volatile("bar.sync %0, 128;" :: "r"(id) : "memory");
}
DEV void sts128(uint32_t addr, uint32_t a, uint32_t b, uint32_t c, uint32_t d) {
    asm volatile("st.shared.v4.u32 [%0], {%1, %2, %3, %4};"
        :: "r"(addr), "r"(a), "r"(b), "r"(c), "r"(d) : "memory");
}

// ---------------- per-batch bias: c[b] = b1 + new_nodes[b] @ W1[128:256] ----------------
__device__ float g_cbias[BATCH * 256];

__global__ void cbias_kernel(const float* __restrict__ new_nodes,
                             const float* __restrict__ W1,
                             const float* __restrict__ b1) {
    int b = blockIdx.x;
    int n = threadIdx.x;
    float acc = b1[n];
    const float* nb = new_nodes + (size_t)b * HID;
#pragma unroll 8
    for (int f = 0; f < HID; ++f)
        acc = fmaf(nb[f], W1[(size_t)(HID + f) * 256 + n], acc);
    g_cbias[b * 256 + n] = acc;
}

// ---------------- main fused kernel ----------------
__global__ void __launch_bounds__(256, 1)
edge_mlp_kernel(const float* __restrict__ nodes,   // [NROWS,128]
                const float* __restrict__ W1,      // [256,256]
                const float* __restrict__ W2,      // [256,64]
                const float* __restrict__ W3,      // [64]
                const float* __restrict__ b2,      // [64]
                const float* __restrict__ b3,      // [1]
                float* __restrict__ out)           // [NROWS]
{
    extern __shared__ char smem[];
    const uint32_t sb = s2u(smem);
    const int tid  = threadIdx.x;
    const int wid  = tid >> 5;
    const int lane = tid & 31;
    const int l7   = lane & 7;
    const int l3   = lane & 3;
    const int rsel = (lane >> 3) & 1;   // row-half selector for ldmatrix
    const int usub = lane >> 4;         // k-unit selector for ldmatrix
    const int g    = tid >> 7;          // group 0: warps 0-3 (rows 0-127); group 1: warps 4-7
    const int gtid = tid & 127;

    float* w3_s = reinterpret_cast<float*>(smem + OFF_W3);
    float* b2_s = reinterpret_cast<float*>(smem + OFF_B2C);
    float* b3_s = reinterpret_cast<float*>(smem + OFF_B3);
    uint32_t* cs_h = reinterpret_cast<uint32_t*>(smem + OFF_CS) + g * 128;  // half2[128] per group
    float* stg  = reinterpret_cast<float*>(smem + OFF_STG);

    const uint32_t sbar = sb + OFF_BAR;

    if (tid == 0) mbar_init(sbar, 1);
    __syncthreads();

    // load 0: tile blockIdx.x, rows [0,128) — issued ASAP, overlaps weight conversion
    if (tid == 0) {
        mbar_expect(sbar, 65536);
        bulk_g2s(sb + OFF_STG, nodes + (size_t)blockIdx.x * (256 * HID), 65536, sbar);
    }

    // small constants
    if (tid < 64) { w3_s[tid] = W3[tid]; b2_s[tid] = b2[tid]; }
    if (tid == 0) b3_s[0] = b3[0];

    // B1: [n=256][k=128] f16, 256B rows, XOR swizzle (unit16B ^ row&7). B1[n][k]=W1[k*256+n]
    {
        const int n = tid;
#pragma unroll 4
        for (int kp = 0; kp < 64; ++kp) {
            float a = W1[(size_t)(2 * kp) * 256 + n];
            float b = W1[(size_t)(2 * kp + 1) * 256 + n];
            uint32_t addr = (uint32_t)(n * 256 + (((kp >> 2) ^ (n & 7)) << 4) + (kp & 3) * 4);
            *reinterpret_cast<uint32_t*>(smem + OFF_B1 + addr) = pack2(a, b);
        }
    }
    // B2: [n=64][k=256] f16, 512B rows, same swizzle. B2[n][k]=W2[k*64+n]
    {
#pragma unroll 4
        for (int j = 0; j < 32; ++j) {
            int idx = tid + j * 256;
            int n  = idx & 63;
            int kp = idx >> 6;              // 0..127
            float a = W2[(size_t)(2 * kp) * 64 + n];
            float b = W2[(size_t)(2 * kp + 1) * 64 + n];
            uint32_t addr = (uint32_t)(n * 512 + (((kp >> 2) ^ (n & 7)) << 4) + (kp & 3) * 4);
            *reinterpret_cast<uint32_t*>(smem + OFF_B2 + addr) = pack2(a, b);
        }
    }
    __syncthreads();
    // after this point: NO full-CTA barriers; the two groups run decoupled.

    // per-warp ldmatrix lane bases
    const uint32_t aBase0 = sb + OFF_A1 + (uint32_t)((wid * 32      + l7 + (rsel << 3)) * 256);
    const uint32_t aBase1 = sb + OFF_A1 + (uint32_t)((wid * 32 + 16 + l7 + (rsel << 3)) * 256);
    const uint32_t b1LaneBase = sb + OFF_B1 + (uint32_t)((l7 + (rsel << 3)) * 256);
    const uint32_t b2LaneBase = sb + OFF_B2 + (uint32_t)((l7 + (rsel << 3)) * 512);

    const int grid = gridDim.x;

    for (int t = blockIdx.x; t < NT2; t += grid) {
        // ---- prefetch per-tile bias into regs BEFORE waiting (hides LDG latency) ----
        const int b = t >> 4;
        const float2 cbv = *reinterpret_cast<const float2*>(&g_cbias[b * 256 + 2 * gtid]);

        // ---- wait my group's staged half (parity == g by construction) ----
        mbar_wait(sbar, (uint32_t)g);

        cs_h[gtid] = pack2(cbv.x, cbv.y);   // half2 bias, cols (2*gtid, 2*gtid+1)

        // ---- convert stage fp32 -> f16 swizzled A1 rows [g*128, g*128+128) ----
        // one 16B swizzle unit per iteration: 2x float4 load + STS.128
#pragma unroll 4
        for (int j = 0; j < 16; ++j) {
            int idx = gtid + j * 128;                // 0..2047
            int m   = idx >> 4;                      // local row 0..127
            int u   = idx & 15;                      // 16B unit 0..15
            float4 v0 = reinterpret_cast<const float4*>(stg)[m * 32 + u * 2];
            float4 v1 = reinterpret_cast<const float4*>(stg)[m * 32 + u * 2 + 1];
            uint32_t addr = sb + OFF_A1 +
                (uint32_t)((g * 128 + m) * 256 + ((u ^ (m & 7)) << 4));
            sts128(addr, pack2(v0.x, v0.y), pack2(v0.z, v0.w),
                         pack2(v1.x, v1.y), pack2(v1.z, v1.w));
        }
        named_bar(1 + g);

        // ---- group leader issues the NEXT load (stage buffer now free) ----
        if (gtid == 0) {
            if (g == 0) {
                mbar_expect(sbar, 65536);
                bulk_g2s(sb + OFF_STG, nodes + ((size_t)t * 256 + 128) * HID, 65536, sbar);
            } else if (t + grid < NT2) {
                mbar_expect(sbar, 65536);
                bulk_g2s(sb + OFF_STG, nodes + (size_t)(t + grid) * 256 * HID, 65536, sbar);
            }
        }

        // ---- load A fragments: 32 rows x 128 k -> 2 halves x 8 k-steps ----
        uint32_t areg[2][8][4];
#pragma unroll
        for (int s = 0; s < 8; ++s) {
            ldsm4(areg[0][s], aBase0 + (uint32_t)((((s << 1) + usub) ^ l7) << 4));
            ldsm4(areg[1][s], aBase1 + (uint32_t)((((s << 1) + usub) ^ l7) << 4));
        }

        float c2[2][8][4];
#pragma unroll
        for (int h = 0; h < 2; ++h)
#pragma unroll
            for (int f = 0; f < 8; ++f)
#pragma unroll
                for (int q = 0; q < 4; ++q) c2[h][f][q] = 0.f;

        // ---- fused layers 1+2, TWO 16-col blocks of layer-1 output per iter ----
        for (int pp = 0; pp < 8; ++pp) {
            const int p0 = 2 * pp;
            // f16 accumulators; layout doubles as layer-2 A fragment after bias+relu:
            // c1[pb][h] = {n0.rows g, n0.rows g+8, n1.rows g, n1.rows g+8}
            uint32_t c1[2][2][4];
#pragma unroll
            for (int pb = 0; pb < 2; ++pb)
#pragma unroll
                for (int h = 0; h < 2; ++h)
#pragma unroll
                    for (int q = 0; q < 4; ++q) c1[pb][h][q] = 0u;

            const uint32_t bB0 = b1LaneBase + (uint32_t)(p0 * 16 * 256);
            const uint32_t bB1 = bB0 + 4096;

            // prefetch stream0 s=0
            uint32_t brc0[4];
            ldsm4(brc0, bB0 + (uint32_t)((usub ^ l7) << 4));
#pragma unroll
            for (int s = 0; s < 8; ++s) {
                const uint32_t soff = (uint32_t)((((s << 1) + usub) ^ l7) << 4);
                // stream1 B for this step (hidden by stream0 MMAs below)
                uint32_t br1[4];
                ldsm4(br1, bB1 + soff);
                // stream0 MMAs (brc0 ready)
                mma16816h(&c1[0][0][0], areg[0][s], brc0[0], brc0[2]);
                mma16816h(&c1[0][0][2], areg[0][s], brc0[1], brc0[3]);
                mma16816h(&c1[0][1][0], areg[1][s], brc0[0], brc0[2]);
                mma16816h(&c1[0][1][2], areg[1][s], brc0[1], brc0[3]);
                // prefetch stream0 next step
                uint32_t brn0[4];
                if (s < 7)
                    ldsm4(brn0, bB0 + (uint32_t)(((((s + 1) << 1) + usub) ^ l7) << 4));
                // stream1 MMAs (br1 ready: 4 MMAs of latency cover)
                mma16816h(&c1[1][0][0], areg[0][s], br1[0], br1[2]);
                mma16816h(&c1[1][0][2], areg[0][s], br1[1], br1[3]);
                mma16816h(&c1[1][1][0], areg[1][s], br1[0], br1[2]);
                mma16816h(&c1[1][1][2], areg[1][s], br1[1], br1[3]);
                if (s < 7) {
                    brc0[0] = brn0[0]; brc0[1] = brn0[1]; brc0[2] = brn0[2]; brc0[3] = brn0[3];
                }
            }

            const uint32_t koffA = (uint32_t)((((p0 << 1) + usub) ^ l7) << 4);
            const uint32_t koffB = (uint32_t)(((((p0 + 1) << 1) + usub) ^ l7) << 4);

            // prefetch first layer-2 B fragment for stream A (hidden by bias+relu below)
            uint32_t br2a[4];
            ldsm4(br2a, b2LaneBase + koffA);

            // epilogue-1: in-place half2 bias + relu; c1 IS the layer-2 A fragment
#pragma unroll
            for (int pb = 0; pb < 2; ++pb) {
                const int cbase = (p0 + pb) * 8;            // half2 index base
                const uint32_t bv0 = cs_h[cbase + l3];      // cols n0: 2*l3, 2*l3+1
                const uint32_t bv1 = cs_h[cbase + 4 + l3];  // cols n1 (8..15)
#pragma unroll
                for (int h = 0; h < 2; ++h) {
                    c1[pb][h][0] = hadd2_relu(c1[pb][h][0], bv0);
                    c1[pb][h][1] = hadd2_relu(c1[pb][h][1], bv0);
                    c1[pb][h][2] = hadd2_relu(c1[pb][h][2], bv1);
                    c1[pb][h][3] = hadd2_relu(c1[pb][h][3], bv1);
                }
            }

            // layer-2 partial: k-steps p0, p0+1; SW-pipelined B2 fetches
#pragma unroll
            for (int p2 = 0; p2 < 4; ++p2) {
                const uint32_t rowOff = (uint32_t)(p2 * 16 * 512);
                uint32_t br2b[4];
                ldsm4(br2b, b2LaneBase + rowOff + koffB);
                uint32_t br2an[4];
                if (p2 < 3)
                    ldsm4(br2an, b2LaneBase + (uint32_t)((p2 + 1) * 16 * 512) + koffA);
                // stream A MMAs (br2a ready)
                mma16816(c2[0][2 * p2],     c1[0][0], br2a[0], br2a[2]);
                mma16816(c2[0][2 * p2 + 1], c1[0][0], br2a[1], br2a[3]);
                mma16816(c2[1][2 * p2],     c1[0][1], br2a[0], br2a[2]);
                mma16816(c2[1][2 * p2 + 1], c1[0][1], br2a[1], br2a[3]);
                // stream B MMAs (br2b ready after A's 4 MMAs)
                mma16816(c2[0][2 * p2],     c1[1][0], br2b[0], br2b[2]);
                mma16816(c2[0][2 * p2 + 1], c1[1][0], br2b[1], br2b[3]);
                mma16816(c2[1][2 * p2],     c1[1][1], br2b[0], br2b[2]);
                mma16816(c2[1][2 * p2 + 1], c1[1][1], br2b[1], br2b[3]);
                if (p2 < 3) {
                    br2a[0] = br2an[0]; br2a[1] = br2an[1]; br2a[2] = br2an[2]; br2a[3] = br2an[3];
                }
            }
        }

        // ---- epilogue 2: relu(C2 + b2) . W3 + b3 -> sigmoid -> out ----
        const float bias3 = b3_s[0];
#pragma unroll
        for (int h = 0; h < 2; ++h) {
            float accl = 0.f, acch = 0.f;
#pragma unroll
            for (int f2 = 0; f2 < 8; ++f2) {
                const int col = f2 * 8 + l3 * 2;
                float w0 = w3_s[col], w1 = w3_s[col + 1];
                float bb0 = b2_s[col], bb1 = b2_s[col + 1];
                accl = fmaf(fmaxf(c2[h][f2][0] + bb0, 0.f), w0, accl);
                accl = fmaf(fmaxf(c2[h][f2][1] + bb1, 0.f), w1, accl);
                acch = fmaf(fmaxf(c2[h][f2][2] + bb0, 0.f), w0, acch);
                acch = fmaf(fmaxf(c2[h][f2][3] + bb1, 0.f), w1, acch);
            }
            accl += __shfl_xor_sync(0xffffffffu, accl, 1);
            accl += __shfl_xor_sync(0xffffffffu, accl, 2);
            acch += __shfl_xor_sync(0xffffffffu, acch, 1);
            acch += __shfl_xor_sync(0xffffffffu, acch, 2);
            if (l3 == 0) {
                const int row = t * 256 + wid * 32 + 16 * h + (lane >> 2);
                out[row]     = 1.f / (1.f + __expf(-(accl + bias3)));
                out[row + 8] = 1.f / (1.f + __expf(-(acch + bias3)));
            }
        }

        named_bar(1 + g);   // protect cs_h (and ordering) for the next iteration
    }
}

// ---------------- launch ----------------
extern "C" void kernel_launch(void* const* d_in, const int* in_sizes, int n_in,
                              void* d_out, int out_size) {
    const float* nodes = (const float*)d_in[0];   // [128,4096,128]
    const float* newn  = (const float*)d_in[1];   // [128,1,128]
    const float* W1    = (const float*)d_in[2];   // [256,256]
    const float* b1    = (const float*)d_in[3];   // [256]
    const float* W2    = (const float*)d_in[4];   // [256,64]
    const float* b2    = (const float*)d_in[5];   // [64]
    const float* W3    = (const float*)d_in[6];   // [64,1]
    const float* b3    = (const float*)d_in[7];   // [1]
    float* out = (float*)d_out;

    (void)in_sizes; (void)n_in; (void)out_size;

    cudaFuncSetAttribute(edge_mlp_kernel,
                         cudaFuncAttributeMaxDynamicSharedMemorySize, SMEM_BYTES);

    int nsm = 148;
    cudaDeviceGetAttribute(&nsm, cudaDevAttrMultiProcessorCount, 0);
    if (nsm <= 0) nsm = 148;
    if (nsm > NT2) nsm = NT2;

    cbias_kernel<<<BATCH, 256>>>(newn, W1, b1);
    edge_mlp_kernel<<<nsm, 256, SMEM_BYTES>>>(nodes, W1, W2, W3, b2, b3, out);
}

// round 9
// speedup vs baseline: 1.2632x; 1.0282x over previous
#include <cuda_runtime.h>
#include <cuda_fp16.h>
#include <cstdint>

#define DEV __device__ __forceinline__

// ---------------- problem constants ----------------
static constexpr int HID    = 128;
static constexpr int BATCH  = 128;
static constexpr int NROWS  = 128 * 4096;     // 524288
static constexpr int NT2    = NROWS / 256;    // 2048 tiles of 256 rows

// ---------------- SMEM layout (byte offsets) ----------------
static constexpr int OFF_BAR  = 0;                  // mbarrier (8B)
static constexpr int OFF_W3   = 64;                 // 64 f32
static constexpr int OFF_B2C  = 320;                // 64 f32
static constexpr int OFF_B3   = 576;                // 1 f32
static constexpr int OFF_CS   = 1024;               // [2][128] half2 bias (1KB)
static constexpr int OFF_A1   = 3072;               // 256 x 128 f16 swizzled (64KB)
static constexpr int OFF_B1   = OFF_A1 + 65536;     // 256n x 128k f16 swizzled (64KB)
static constexpr int OFF_B2   = OFF_B1 + 65536;     // 64n x 256k f16 swizzled (32KB)
static constexpr int OFF_STG  = OFF_B2 + 32768;     // fp32 stage: 128 rows x 128 (64KB)
static constexpr int SMEM_BYTES = OFF_STG + 65536;  // 232448 == opt-in max

// ---------------- helpers ----------------
DEV uint32_t s2u(const void* p) {
    uint32_t a;
    asm("{ .reg .u64 t; cvta.to.shared.u64 t, %1; cvt.u32.u64 %0, t; }" : "=r"(a) : "l"(p));
    return a;
}
DEV uint32_t pack2(float a, float b) {
    __half2 h = __floats2half2_rn(a, b);
    return *reinterpret_cast<uint32_t*>(&h);
}
DEV uint32_t hadd2_relu(uint32_t x, uint32_t bias) {
    __half2 v = __hadd2(*reinterpret_cast<__half2*>(&x),
                        *reinterpret_cast<__half2*>(&bias));
    __half2 z = __floats2half2_rn(0.f, 0.f);
    __half2 r = __hmax2(v, z);
    return *reinterpret_cast<uint32_t*>(&r);
}
DEV void mbar_init(uint32_t mbar, uint32_t cnt) {
    asm volatile("mbarrier.init.shared.b64 [%0], %1;" :: "r"(mbar), "r"(cnt) : "memory");
}
DEV void mbar_expect(uint32_t mbar, uint32_t bytes) {
    asm volatile("mbarrier.arrive.expect_tx.shared.b64 _, [%0], %1;" :: "r"(mbar), "r"(bytes) : "memory");
}
DEV void mbar_wait(uint32_t mbar, uint32_t parity) {
    asm volatile(
        "{\n\t.reg .pred P;\n\t"
        "LW%=:\n\t"
        "mbarrier.try_wait.parity.acquire.cta.shared::cta.b64 P, [%0], %1, 0x989680;\n\t"
        "@P bra LD%=;\n\t"
        "bra LW%=;\n\t"
        "LD%=:\n\t}"
        :: "r"(mbar), "r"(parity) : "memory");
}
DEV void bulk_g2s(uint32_t dst, const void* src, uint32_t bytes, uint32_t mbar) {
    asm volatile(
        "cp.async.bulk.shared::cta.global.mbarrier::complete_tx::bytes [%0], [%1], %2, [%3];"
        :: "r"(dst), "l"(src), "r"(bytes), "r"(mbar) : "memory");
}
DEV void ldsm4(uint32_t* r, uint32_t addr) {
    asm volatile("ldmatrix.sync.aligned.m8n8.x4.shared.b16 {%0,%1,%2,%3}, [%4];"
        : "=r"(r[0]), "=r"(r[1]), "=r"(r[2]), "=r"(r[3]) : "r"(addr));
}
// f32-accumulate MMA (layer 2)
DEV void mma16816(float* c, const uint32_t* a, uint32_t b0, uint32_t b1) {
    asm volatile(
        "mma.sync.aligned.m16n8k16.row.col.f32.f16.f16.f32 "
        "{%0,%1,%2,%3}, {%4,%5,%6,%7}, {%8,%9}, {%0,%1,%2,%3};"
        : "+f"(c[0]), "+f"(c[1]), "+f"(c[2]), "+f"(c[3])
        : "r"(a[0]), "r"(a[1]), "r"(a[2]), "r"(a[3]), "r"(b0), "r"(b1));
}
// f16-accumulate MMA (layer 1) — D fragment is A-fragment-layout compatible
DEV void mma16816h(uint32_t* c, const uint32_t* a, uint32_t b0, uint32_t b1) {
    asm volatile(
        "mma.sync.aligned.m16n8k16.row.col.f16.f16.f16.f16 "
        "{%0,%1}, {%2,%3,%4,%5}, {%6,%7}, {%0,%1};"
        : "+r"(c[0]), "+r"(c[1])
        : "r"(a[0]), "r"(a[1]), "r"(a[2]), "r"(a[3]), "r"(b0), "r"(b1));
}
DEV void named_bar(int id) {
    asm volatile("bar.sync %0, 128;" :: "r"(id) : "memory");
}
DEV void sts128(uint32_t addr, uint32_t a, uint32_t b, uint32_t c, uint32_t d) {
    asm volatile("st.shared.v4.u32 [%0], {%1, %2, %3, %4};"
        :: "r"(addr), "r"(a), "r"(b), "r"(c), "r"(d) : "memory");
}

// ---------------- globals: per-batch bias + single-launch sync flags ----------------
__device__ float g_cbias[BATCH * 256];
__device__ int   g_done   = 0;   // producers completed (0..128)
__device__ int   g_passed = 0;   // CTAs past the spin (0..gridDim.x)

// ---------------- main fused kernel (single launch) ----------------
__global__ void __launch_bounds__(256, 1)
edge_mlp_kernel(const float* __restrict__ nodes,   // [NROWS,128]
                const float* __restrict__ newn,    // [BATCH,128]
                const float* __restrict__ W1,      // [256,256]
                const float* __restrict__ b1,      // [256]
                const float* __restrict__ W2,      // [256,64]
                const float* __restrict__ W3,      // [64]
                const float* __restrict__ b2,      // [64]
                const float* __restrict__ b3,      // [1]
                float* __restrict__ out)           // [NROWS]
{
    extern __shared__ char smem[];
    const uint32_t sb = s2u(smem);
    const int tid  = threadIdx.x;
    const int wid  = tid >> 5;
    const int lane = tid & 31;
    const int l7   = lane & 7;
    const int l3   = lane & 3;
    const int rsel = (lane >> 3) & 1;   // row-half selector for ldmatrix
    const int usub = lane >> 4;         // k-unit selector for ldmatrix
    const int g    = tid >> 7;          // group 0: warps 0-3 (rows 0-127); group 1: warps 4-7
    const int gtid = tid & 127;

    float* w3_s = reinterpret_cast<float*>(smem + OFF_W3);
    float* b2_s = reinterpret_cast<float*>(smem + OFF_B2C);
    float* b3_s = reinterpret_cast<float*>(smem + OFF_B3);
    uint32_t* cs_h = reinterpret_cast<uint32_t*>(smem + OFF_CS) + g * 128;  // half2[128] per group
    float* stg  = reinterpret_cast<float*>(smem + OFF_STG);

    const uint32_t sbar = sb + OFF_BAR;

    if (tid == 0) mbar_init(sbar, 1);
    __syncthreads();

    // load 0: tile blockIdx.x, rows [0,128) — issued ASAP, overlaps prologue
    if (tid == 0) {
        mbar_expect(sbar, 65536);
        bulk_g2s(sb + OFF_STG, nodes + (size_t)blockIdx.x * (256 * HID), 65536, sbar);
    }

    // small constants
    if (tid < 64) { w3_s[tid] = W3[tid]; b2_s[tid] = b2[tid]; }
    if (tid == 0) b3_s[0] = b3[0];

    // ---- producer CTAs compute per-batch bias c[b] = b1 + new[b] @ W1[128:256] ----
    if (blockIdx.x < BATCH) {
        const int b = blockIdx.x;
        const int n = tid;
        float acc = b1[n];
        const float* nb = newn + (size_t)b * HID;
#pragma unroll 8
        for (int f = 0; f < HID; ++f)
            acc = fmaf(nb[f], W1[(size_t)(HID + f) * 256 + n], acc);
        g_cbias[b * 256 + n] = acc;
        __threadfence();
        __syncthreads();
        if (tid == 0) atomicAdd(&g_done, 1);
    }

    // B1: [n=256][k=128] f16, 256B rows, XOR swizzle (unit16B ^ row&7). B1[n][k]=W1[k*256+n]
    {
        const int n = tid;
#pragma unroll 4
        for (int kp = 0; kp < 64; ++kp) {
            float a = W1[(size_t)(2 * kp) * 256 + n];
            float b = W1[(size_t)(2 * kp + 1) * 256 + n];
            uint32_t addr = (uint32_t)(n * 256 + (((kp >> 2) ^ (n & 7)) << 4) + (kp & 3) * 4);
            *reinterpret_cast<uint32_t*>(smem + OFF_B1 + addr) = pack2(a, b);
        }
    }
    // B2: [n=64][k=256] f16, 512B rows, same swizzle. B2[n][k]=W2[k*64+n]
    {
#pragma unroll 4
        for (int j = 0; j < 32; ++j) {
            int idx = tid + j * 256;
            int n  = idx & 63;
            int kp = idx >> 6;              // 0..127
            float a = W2[(size_t)(2 * kp) * 64 + n];
            float b = W2[(size_t)(2 * kp + 1) * 64 + n];
            uint32_t addr = (uint32_t)(n * 512 + (((kp >> 2) ^ (n & 7)) << 4) + (kp & 3) * 4);
            *reinterpret_cast<uint32_t*>(smem + OFF_B2 + addr) = pack2(a, b);
        }
    }
    __syncthreads();

    // ---- wait for all producers, then self-reset flags for graph replay ----
    if (tid == 0) {
        while (*((volatile int*)&g_done) < BATCH) { }
        if (atomicAdd(&g_passed, 1) == (int)gridDim.x - 1) {
            // last CTA through: everyone has passed the spin; reset for next launch
            g_done = 0;
            g_passed = 0;
            __threadfence();
        }
    }
    __syncthreads();
    // after this point: NO full-CTA barriers; the two groups run decoupled.

    // per-warp ldmatrix lane bases
    const uint32_t aBase0 = sb + OFF_A1 + (uint32_t)((wid * 32      + l7 + (rsel << 3)) * 256);
    const uint32_t aBase1 = sb + OFF_A1 + (uint32_t)((wid * 32 + 16 + l7 + (rsel << 3)) * 256);
    const uint32_t b1LaneBase = sb + OFF_B1 + (uint32_t)((l7 + (rsel << 3)) * 256);
    const uint32_t b2LaneBase = sb + OFF_B2 + (uint32_t)((l7 + (rsel << 3)) * 512);
    const uint32_t soff0 = (uint32_t)((usub ^ l7) << 4);   // s=0 fragment offset

    const int grid = gridDim.x;

    for (int t = blockIdx.x; t < NT2; t += grid) {
        // ---- prefetch per-tile bias into regs BEFORE waiting (hides LDG latency) ----
        const int b = t >> 4;
        const float2 cbv = *reinterpret_cast<const float2*>(&g_cbias[b * 256 + 2 * gtid]);

        // ---- wait my group's staged half (parity == g by construction) ----
        mbar_wait(sbar, (uint32_t)g);

        cs_h[gtid] = pack2(cbv.x, cbv.y);   // half2 bias, cols (2*gtid, 2*gtid+1)

        // ---- convert stage fp32 -> f16 swizzled A1 rows [g*128, g*128+128) ----
#pragma unroll 4
        for (int j = 0; j < 16; ++j) {
            int idx = gtid + j * 128;                // 0..2047
            int m   = idx >> 4;                      // local row 0..127
            int u   = idx & 15;                      // 16B unit 0..15
            float4 v0 = reinterpret_cast<const float4*>(stg)[m * 32 + u * 2];
            float4 v1 = reinterpret_cast<const float4*>(stg)[m * 32 + u * 2 + 1];
            uint32_t addr = sb + OFF_A1 +
                (uint32_t)((g * 128 + m) * 256 + ((u ^ (m & 7)) << 4));
            sts128(addr, pack2(v0.x, v0.y), pack2(v0.z, v0.w),
                         pack2(v1.x, v1.y), pack2(v1.z, v1.w));
        }
        named_bar(1 + g);

        // ---- group leader issues the NEXT load (stage buffer now free) ----
        if (gtid == 0) {
            if (g == 0) {
                mbar_expect(sbar, 65536);
                bulk_g2s(sb + OFF_STG, nodes + ((size_t)t * 256 + 128) * HID, 65536, sbar);
            } else if (t + grid < NT2) {
                mbar_expect(sbar, 65536);
                bulk_g2s(sb + OFF_STG, nodes + (size_t)(t + grid) * 256 * HID, 65536, sbar);
            }
        }

        // ---- load A fragments: 32 rows x 128 k -> 2 halves x 8 k-steps ----
        uint32_t areg[2][8][4];
#pragma unroll
        for (int s = 0; s < 8; ++s) {
            ldsm4(areg[0][s], aBase0 + (uint32_t)((((s << 1) + usub) ^ l7) << 4));
            ldsm4(areg[1][s], aBase1 + (uint32_t)((((s << 1) + usub) ^ l7) << 4));
        }

        float c2[2][8][4];
#pragma unroll
        for (int h = 0; h < 2; ++h)
#pragma unroll
            for (int f = 0; f < 8; ++f)
#pragma unroll
                for (int q = 0; q < 4; ++q) c2[h][f][q] = 0.f;

        // ---- fused layers 1+2, TWO 16-col blocks per iter; brc0 pipelined ACROSS pp ----
        uint32_t brc0[4];
        ldsm4(brc0, b1LaneBase + soff0);   // pp=0, s=0
        for (int pp = 0; pp < 8; ++pp) {
            const int p0 = 2 * pp;
            uint32_t c1[2][2][4];
#pragma unroll
            for (int pb = 0; pb < 2; ++pb)
#pragma unroll
                for (int h = 0; h < 2; ++h)
#pragma unroll
                    for (int q = 0; q < 4; ++q) c1[pb][h][q] = 0u;

            const uint32_t bB0 = b1LaneBase + (uint32_t)(p0 * 16 * 256);
            const uint32_t bB1 = bB0 + 4096;

#pragma unroll
            for (int s = 0; s < 8; ++s) {
                const uint32_t soff = (uint32_t)((((s << 1) + usub) ^ l7) << 4);
                // stream1 B for this step (hidden by stream0 MMAs below)
                uint32_t br1[4];
                ldsm4(br1, bB1 + soff);
                // stream0 MMAs (brc0 ready)
                mma16816h(&c1[0][0][0], areg[0][s], brc0[0], brc0[2]);
                mma16816h(&c1[0][0][2], areg[0][s], brc0[1], brc0[3]);
                mma16816h(&c1[0][1][0], areg[1][s], brc0[0], brc0[2]);
                mma16816h(&c1[0][1][2], areg[1][s], brc0[1], brc0[3]);
                // prefetch stream0: next s, or s=0 of NEXT pp (pp=7 tail reads into B2
                // region — in-bounds smem, value never consumed)
                uint32_t brn0[4];
                ldsm4(brn0, (s < 7)
                        ? bB0 + (uint32_t)(((((s + 1) << 1) + usub) ^ l7) << 4)
                        : bB0 + 8192 + soff0);
                // stream1 MMAs (br1 ready: 4 MMAs of latency cover)
                mma16816h(&c1[1][0][0], areg[0][s], br1[0], br1[2]);
                mma16816h(&c1[1][0][2], areg[0][s], br1[1], br1[3]);
                mma16816h(&c1[1][1][0], areg[1][s], br1[0], br1[2]);
                mma16816h(&c1[1][1][2], areg[1][s], br1[1], br1[3]);
                brc0[0] = brn0[0]; brc0[1] = brn0[1]; brc0[2] = brn0[2]; brc0[3] = brn0[3];
            }

            const uint32_t koffA = (uint32_t)((((p0 << 1) + usub) ^ l7) << 4);
            const uint32_t koffB = (uint32_t)(((((p0 + 1) << 1) + usub) ^ l7) << 4);

            // prefetch first layer-2 B fragment for stream A (hidden by bias+relu below)
            uint32_t br2a[4];
            ldsm4(br2a, b2LaneBase + koffA);

            // epilogue-1: in-place half2 bias + relu; c1 IS the layer-2 A fragment
#pragma unroll
            for (int pb = 0; pb < 2; ++pb) {
                const int cbase = (p0 + pb) * 8;            // half2 index base
                const uint32_t bv0 = cs_h[cbase + l3];      // cols n0: 2*l3, 2*l3+1
                const uint32_t bv1 = cs_h[cbase + 4 + l3];  // cols n1 (8..15)
#pragma unroll
                for (int h = 0; h < 2; ++h) {
                    c1[pb][h][0] = hadd2_relu(c1[pb][h][0], bv0);
                    c1[pb][h][1] = hadd2_relu(c1[pb][h][1], bv0);
                    c1[pb][h][2] = hadd2_relu(c1[pb][h][2], bv1);
                    c1[pb][h][3] = hadd2_relu(c1[pb][h][3], bv1);
                }
            }

            // layer-2 partial: k-steps p0, p0+1; SW-pipelined B2 fetches
#pragma unroll
            for (int p2 = 0; p2 < 4; ++p2) {
                const uint32_t rowOff = (uint32_t)(p2 * 16 * 512);
                uint32_t br2b[4];
                ldsm4(br2b, b2LaneBase + rowOff + koffB);
                uint32_t br2an[4];
                if (p2 < 3)
                    ldsm4(br2an, b2LaneBase + (uint32_t)((p2 + 1) * 16 * 512) + koffA);
                // stream A MMAs (br2a ready)
                mma16816(c2[0][2 * p2],     c1[0][0], br2a[0], br2a[2]);
                mma16816(c2[0][2 * p2 + 1], c1[0][0], br2a[1], br2a[3]);
                mma16816(c2[1][2 * p2],     c1[0][1], br2a[0], br2a[2]);
                mma16816(c2[1][2 * p2 + 1], c1[0][1], br2a[1], br2a[3]);
                // stream B MMAs (br2b ready after A's 4 MMAs)
                mma16816(c2[0][2 * p2],     c1[1][0], br2b[0], br2b[2]);
                mma16816(c2[0][2 * p2 + 1], c1[1][0], br2b[1], br2b[3]);
                mma16816(c2[1][2 * p2],     c1[1][1], br2b[0], br2b[2]);
                mma16816(c2[1][2 * p2 + 1], c1[1][1], br2b[1], br2b[3]);
                if (p2 < 3) {
                    br2a[0] = br2an[0]; br2a[1] = br2an[1]; br2a[2] = br2an[2]; br2a[3] = br2an[3];
                }
            }
        }

        // ---- epilogue 2: relu(C2 + b2) . W3 + b3 -> sigmoid -> out ----
        const float bias3 = b3_s[0];
#pragma unroll
        for (int h = 0; h < 2; ++h) {
            float accl = 0.f, acch = 0.f;
#pragma unroll
            for (int f2 = 0; f2 < 8; ++f2) {
                const int col = f2 * 8 + l3 * 2;
                float w0 = w3_s[col], w1 = w3_s[col + 1];
                float bb0 = b2_s[col], bb1 = b2_s[col + 1];
                accl = fmaf(fmaxf(c2[h][f2][0] + bb0, 0.f), w0, accl);
                accl = fmaf(fmaxf(c2[h][f2][1] + bb1, 0.f), w1, accl);
                acch = fmaf(fmaxf(c2[h][f2][2] + bb0, 0.f), w0, acch);
                acch = fmaf(fmaxf(c2[h][f2][3] + bb1, 0.f), w1, acch);
            }
            accl += __shfl_xor_sync(0xffffffffu, accl, 1);
            accl += __shfl_xor_sync(0xffffffffu, accl, 2);
            acch += __shfl_xor_sync(0xffffffffu, acch, 1);
            acch += __shfl_xor_sync(0xffffffffu, acch, 2);
            if (l3 == 0) {
                const int row = t * 256 + wid * 32 + 16 * h + (lane >> 2);
                out[row]     = 1.f / (1.f + __expf(-(accl + bias3)));
                out[row + 8] = 1.f / (1.f + __expf(-(acch + bias3)));
            }
        }

        named_bar(1 + g);   // protect cs_h (and ordering) for the next iteration
    }
}

// ---------------- launch ----------------
extern "C" void kernel_launch(void* const* d_in, const int* in_sizes, int n_in,
                              void* d_out, int out_size) {
    const float* nodes = (const float*)d_in[0];   // [128,4096,128]
    const float* newn  = (const float*)d_in[1];   // [128,1,128]
    const float* W1    = (const float*)d_in[2];   // [256,256]
    const float* b1    = (const float*)d_in[3];   // [256]
    const float* W2    = (const float*)d_in[4];   // [256,64]
    const float* b2    = (const float*)d_in[5];   // [64]
    const float* W3    = (const float*)d_in[6];   // [64,1]
    const float* b3    = (const float*)d_in[7];   // [1]
    float* out = (float*)d_out;

    (void)in_sizes; (void)n_in; (void)out_size;

    cudaFuncSetAttribute(edge_mlp_kernel,
                         cudaFuncAttributeMaxDynamicSharedMemorySize, SMEM_BYTES);

    int nsm = 148;
    cudaDeviceGetAttribute(&nsm, cudaDevAttrMultiProcessorCount, 0);
    if (nsm <= 0) nsm = 148;
    if (nsm > NT2) nsm = NT2;

    edge_mlp_kernel<<<nsm, 256, SMEM_BYTES>>>(nodes, newn, W1, b1, W2, W3, b2, b3, out);
}